// round 12
// baseline (speedup 1.0000x reference)
#include <cuda_runtime.h>
#include <cuda_bf16.h>
#include <math.h>
#include <stdint.h>

namespace {
constexpr int N      = 256;
constexpr int NSTEPS = 32;
constexpr int NIMG   = 384;                  // 128 batch * 3 channels

// fp32 M-builder tile
constexpr int BM = 128, BN = 128, BK = 16;
constexpr int LDSW = BM + 4;

// ---- k_mm smem maps (bytes) ----
// MODE 1: M tiles (A hi/lo, double): d*20480, AL=+10240
//         conv dest (B hi/lo, double): 40960 + d*17408, BL=+8704 (stride 136 elem)
constexpr int M1_CV   = 40960;
constexpr int M1_SMEM = 75776;
// MODE 2: all-bf16 double buffers: d*40960: TH=0, TL=10240, BH=20480, BL=30720
constexpr int M2_SMEM = 81920;
}

// ---------------- device globals ----------------
__device__ float g_D[N * N];
__device__ float g_E[NSTEPS * N];
__device__ __align__(16) __nv_bfloat16 g_Mh[NSTEPS * N * N];
__device__ __align__(16) __nv_bfloat16 g_Ml[NSTEPS * N * N];
__device__ __align__(16) __nv_bfloat16 g_Th[NIMG * N * N];
__device__ __align__(16) __nv_bfloat16 g_Tl[NIMG * N * N];

// ---------------- helpers ----------------
__device__ __forceinline__ uint32_t smem_u32(const void* p) {
    uint32_t a;
    asm("{ .reg .u64 t; cvta.to.shared.u64 t, %1; cvt.u32.u64 %0, t; }" : "=r"(a) : "l"(p));
    return a;
}
__device__ __forceinline__ void cp16(uint32_t s, const void* g) {
    asm volatile("cp.async.cg.shared.global [%0], [%1], 16;" :: "r"(s), "l"(g) : "memory");
}
__device__ __forceinline__ void cp_commit() {
    asm volatile("cp.async.commit_group;" ::: "memory");
}
__device__ __forceinline__ void cp_wait0() {
    asm volatile("cp.async.wait_group 0;" ::: "memory");
}
__device__ __forceinline__ void ldsm4(uint32_t* r, uint32_t a) {
    asm volatile("ldmatrix.sync.aligned.m8n8.x4.shared.b16 {%0,%1,%2,%3}, [%4];"
                 : "=r"(r[0]), "=r"(r[1]), "=r"(r[2]), "=r"(r[3]) : "r"(a));
}
__device__ __forceinline__ void ldsm4t(uint32_t* r, uint32_t a) {
    asm volatile("ldmatrix.sync.aligned.m8n8.x4.trans.shared.b16 {%0,%1,%2,%3}, [%4];"
                 : "=r"(r[0]), "=r"(r[1]), "=r"(r[2]), "=r"(r[3]) : "r"(a));
}
__device__ __forceinline__ void mma_bf16(float* d, const uint32_t* a, uint32_t b0, uint32_t b1) {
    asm volatile(
        "mma.sync.aligned.m16n8k16.row.col.f32.bf16.bf16.f32 "
        "{%0,%1,%2,%3}, {%4,%5,%6,%7}, {%8,%9}, {%0,%1,%2,%3};"
        : "+f"(d[0]), "+f"(d[1]), "+f"(d[2]), "+f"(d[3])
        : "r"(a[0]), "r"(a[1]), "r"(a[2]), "r"(a[3]), "r"(b0), "r"(b1));
}
__device__ __forceinline__ uint32_t pkbf2(float a, float b) {
    __nv_bfloat162 t = __floats2bfloat162_rn(a, b);
    return reinterpret_cast<uint32_t&>(t);
}
__device__ __forceinline__ void split8(const float* v, uint4& H, uint4& L) {
    float h[8], l[8];
#pragma unroll
    for (int i = 0; i < 8; i++) {
        __nv_bfloat16 b = __float2bfloat16_rn(v[i]);
        h[i] = __bfloat162float(b);
        l[i] = v[i] - h[i];
    }
    H = make_uint4(pkbf2(h[0], h[1]), pkbf2(h[2], h[3]), pkbf2(h[4], h[5]), pkbf2(h[6], h[7]));
    L = make_uint4(pkbf2(l[0], l[1]), pkbf2(l[2], l[3]), pkbf2(l[4], l[5]), pkbf2(l[6], l[7]));
}
__device__ __forceinline__ void split4(float4 v, uint2& H, uint2& L) {
    float vv[4] = {v.x, v.y, v.z, v.w};
    float h[4], l[4];
#pragma unroll
    for (int i = 0; i < 4; i++) {
        __nv_bfloat16 b = __float2bfloat16_rn(vv[i]);
        h[i] = __bfloat162float(b);
        l[i] = vv[i] - h[i];
    }
    H = make_uint2(pkbf2(h[0], h[1]), pkbf2(h[2], h[3]));
    L = make_uint2(pkbf2(l[0], l[1]), pkbf2(l[2], l[3]));
}

// ---------------- init: D and E ----------------
__global__ void k_init(const float* __restrict__ sigmas) {
    int k = blockIdx.x, n = threadIdx.x;
    int p = ((2 * n + 1) * k) & (4 * N - 1);
    double v = sqrt(2.0 / (double)N) * cos(M_PI * (double)p / (double)(2 * N));
    if (k == 0) v *= 0.7071067811865476;
    g_D[k * N + n] = (float)v;
    if (k < NSTEPS) {
        float sig = sigmas[k];
        float t = 0.5f * sig * sig;
        float f = (float)M_PI * (float)n / (float)N;
        g_E[k * N + n] = expf(-f * f * t);
    }
}

// ---------------- fp32 builder: M_s = (D diag(e)) D, split epilogue ----------------
typedef unsigned long long u64;
__device__ __forceinline__ u64 pack2(float x, float y) {
    u64 r; asm("mov.b64 %0, {%1, %2};" : "=l"(r) : "f"(x), "f"(y)); return r;
}
__device__ __forceinline__ void unpack2(u64 v, float& x, float& y) {
    asm("mov.b64 {%0, %1}, %2;" : "=f"(x), "=f"(y) : "l"(v));
}
__device__ __forceinline__ void ffma2(u64& d, u64 a, u64 b) {
    asm("fma.rn.f32x2 %0, %1, %2, %0;" : "+l"(d) : "l"(a), "l"(b));
}

__global__ __launch_bounds__(256, 2) void k_gemm0() {
    __shared__ float As[BK][LDSW];
    __shared__ float Bs[BK][LDSW];
    const int z = blockIdx.z;
    const float* A = g_D;
    const float* B = g_D;
    const float* e = g_E + z * N;
    __nv_bfloat16* Ch = g_Mh + (size_t)z * N * N;
    __nv_bfloat16* Cl = g_Ml + (size_t)z * N * N;

    const int m0 = blockIdx.y * BM, n0 = blockIdx.x * BN;
    const int tid = threadIdx.x;
    const int ty = tid >> 4, tx = tid & 15;
    const int lr = (tid * 2) >> 2, lc = (tid * 2) & 3;
    const int bkr = (tid * 2) >> 5, bnc = (tid * 2) & 31;

    u64 acc[8][4];
#pragma unroll
    for (int i = 0; i < 8; i++)
#pragma unroll
        for (int j = 0; j < 4; j++) acc[i][j] = 0ull;

    for (int k0 = 0; k0 < N; k0 += BK) {
        float4 a0 = *(const float4*)&A[(size_t)(m0 + lr) * N + k0 + lc * 4];
        float4 a1 = *(const float4*)&A[(size_t)(m0 + lr) * N + k0 + lc * 4 + 4];
        a0.x *= e[k0 + lc * 4 + 0]; a0.y *= e[k0 + lc * 4 + 1];
        a0.z *= e[k0 + lc * 4 + 2]; a0.w *= e[k0 + lc * 4 + 3];
        a1.x *= e[k0 + lc * 4 + 4]; a1.y *= e[k0 + lc * 4 + 5];
        a1.z *= e[k0 + lc * 4 + 6]; a1.w *= e[k0 + lc * 4 + 7];
        float4 b0 = *(const float4*)&B[(size_t)(k0 + bkr) * N + n0 + bnc * 4];
        float4 b1 = *(const float4*)&B[(size_t)(k0 + bkr) * N + n0 + bnc * 4 + 4];
        __syncthreads();
        As[lc * 4 + 0][lr] = a0.x; As[lc * 4 + 1][lr] = a0.y;
        As[lc * 4 + 2][lr] = a0.z; As[lc * 4 + 3][lr] = a0.w;
        As[lc * 4 + 4][lr] = a1.x; As[lc * 4 + 5][lr] = a1.y;
        As[lc * 4 + 6][lr] = a1.z; As[lc * 4 + 7][lr] = a1.w;
        *(float4*)&Bs[bkr][bnc * 4]     = b0;
        *(float4*)&Bs[bkr][bnc * 4 + 4] = b1;
        __syncthreads();
#pragma unroll
        for (int kk = 0; kk < BK; kk++) {
            float4 av0 = *(const float4*)&As[kk][ty * 4];
            float4 av1 = *(const float4*)&As[kk][64 + ty * 4];
            float4 bv0 = *(const float4*)&Bs[kk][tx * 4];
            float4 bv1 = *(const float4*)&Bs[kk][64 + tx * 4];
            u64 a2[8] = {pack2(av0.x, av0.x), pack2(av0.y, av0.y), pack2(av0.z, av0.z),
                         pack2(av0.w, av0.w), pack2(av1.x, av1.x), pack2(av1.y, av1.y),
                         pack2(av1.z, av1.z), pack2(av1.w, av1.w)};
            u64 b2[4] = {pack2(bv0.x, bv0.y), pack2(bv0.z, bv0.w),
                         pack2(bv1.x, bv1.y), pack2(bv1.z, bv1.w)};
#pragma unroll
            for (int i = 0; i < 8; i++)
#pragma unroll
                for (int j = 0; j < 4; j++) ffma2(acc[i][j], a2[i], b2[j]);
        }
    }
#pragma unroll
    for (int i = 0; i < 8; i++) {
        const int row = m0 + ((i < 4) ? (ty * 4 + i) : (64 + ty * 4 + (i - 4)));
        float4 c0, c1;
        unpack2(acc[i][0], c0.x, c0.y); unpack2(acc[i][1], c0.z, c0.w);
        unpack2(acc[i][2], c1.x, c1.y); unpack2(acc[i][3], c1.z, c1.w);
        uint2 H0, L0, H1, L1;
        split4(c0, H0, L0);
        split4(c1, H1, L1);
        *(uint2*)&Ch[(size_t)row * N + n0 + tx * 4]      = H0;
        *(uint2*)&Cl[(size_t)row * N + n0 + tx * 4]      = L0;
        *(uint2*)&Ch[(size_t)row * N + n0 + 64 + tx * 4] = H1;
        *(uint2*)&Cl[(size_t)row * N + n0 + 64 + tx * 4] = L1;
    }
}

// ---------------- MODE 1: T = M * X  (A = M hi/lo cp.async; B = X via LDG->split->STS)
// grid (NIMG, 2, 2) = (z, h, nh); 256 threads; warp grid 4m x 2n; warp tile 32x64.
__global__ __launch_bounds__(256, 2) void k_mm1(const float* __restrict__ Xf,
                                                const int* __restrict__ steps) {
    extern __shared__ char sm[];
    const int z = blockIdx.x, h = blockIdx.y, nh = blockIdx.z;
    const int s = steps[z / 3];
    const int t = threadIdx.x, lane = t & 31, wid = t >> 5;
    const int wm = wid >> 1, wn = wid & 1;
    const uint32_t sb = smem_u32(sm);
    const int lr = lane & 15, lc8 = (lane >> 4) * 8;

    const char* Mh_g = (const char*)(g_Mh + (size_t)s * N * N);
    const char* Ml_g = (const char*)(g_Ml + (size_t)s * N * N);
    const float* X_g = Xf + (size_t)z * N * N;

    // per-thread X ownership: row fr (0..31) within chunk, 16 cols at fc
    const int fr = t >> 3;
    const int fc = (t & 7) * 16;

    auto stage_m = [&](int kc, int d) {
        const uint32_t mb = sb + d * 20480;
#pragma unroll
        for (int i = 0; i < 2; i++) {
            int c = t + i * 256, r = c >> 2, q = c & 3;
            size_t go = (size_t)(h * 128 + r) * 512 + kc * 64 + q * 16;
            cp16(mb + r * 80 + q * 16, Mh_g + go);
            cp16(mb + 10240 + r * 80 + q * 16, Ml_g + go);
        }
        cp_commit();
    };

    auto ldg_x = [&](int kc, float4* pf) {
        const float* p = X_g + (size_t)(kc * 32 + fr) * N + nh * 128 + fc;
        pf[0] = *(const float4*)p;
        pf[1] = *(const float4*)(p + 4);
        pf[2] = *(const float4*)(p + 8);
        pf[3] = *(const float4*)(p + 12);
    };

    auto conv_sts = [&](int d, const float4* pf) {
        char* dh = sm + M1_CV + d * 17408 + (fr * 136 + fc) * 2;
        char* dl = dh + 8704;
#pragma unroll
        for (int g = 0; g < 2; g++) {
            float v[8] = {pf[g * 2].x, pf[g * 2].y, pf[g * 2].z, pf[g * 2].w,
                          pf[g * 2 + 1].x, pf[g * 2 + 1].y, pf[g * 2 + 1].z, pf[g * 2 + 1].w};
            uint4 H, L; split8(v, H, L);
            *(uint4*)(dh + g * 16) = H;
            *(uint4*)(dl + g * 16) = L;
        }
    };

    float acc[2][8][4];
#pragma unroll
    for (int a = 0; a < 2; a++)
#pragma unroll
        for (int b = 0; b < 8; b++)
#pragma unroll
            for (int c = 0; c < 4; c++) acc[a][b][c] = 0.0f;

    auto mma_half = [&](int ks, int d) {
        uint32_t Ah[2][4], Al2[2][4], Bf[4][4];
        const uint32_t abase = sb + d * 20480;
#pragma unroll
        for (int mi = 0; mi < 2; mi++) {
            uint32_t a = abase + ((wm * 32 + mi * 16 + lr) * 40 + ks * 16 + lc8) * 2;
            ldsm4(Ah[mi], a);
            ldsm4(Al2[mi], a + 10240);
        }
        const uint32_t bbase = sb + M1_CV + d * 17408;
#pragma unroll
        for (int nj = 0; nj < 4; nj++) {
            uint32_t a = bbase + ((ks * 16 + lr) * 136 + wn * 64 + nj * 16 + lc8) * 2;
            ldsm4t(Bf[nj], a);
        }
        // pass 1: Ah x Bh
#pragma unroll
        for (int mi = 0; mi < 2; mi++)
#pragma unroll
            for (int nj = 0; nj < 4; nj++) {
                mma_bf16(acc[mi][nj * 2],     Ah[mi], Bf[nj][0], Bf[nj][1]);
                mma_bf16(acc[mi][nj * 2 + 1], Ah[mi], Bf[nj][2], Bf[nj][3]);
            }
        // pass 2: Al x Bh
#pragma unroll
        for (int mi = 0; mi < 2; mi++)
#pragma unroll
            for (int nj = 0; nj < 4; nj++) {
                mma_bf16(acc[mi][nj * 2],     Al2[mi], Bf[nj][0], Bf[nj][1]);
                mma_bf16(acc[mi][nj * 2 + 1], Al2[mi], Bf[nj][2], Bf[nj][3]);
            }
        // reload B lo
#pragma unroll
        for (int nj = 0; nj < 4; nj++) {
            uint32_t a = bbase + 8704 + ((ks * 16 + lr) * 136 + wn * 64 + nj * 16 + lc8) * 2;
            ldsm4t(Bf[nj], a);
        }
        // pass 3: Ah x Bl
#pragma unroll
        for (int mi = 0; mi < 2; mi++)
#pragma unroll
            for (int nj = 0; nj < 4; nj++) {
                mma_bf16(acc[mi][nj * 2],     Ah[mi], Bf[nj][0], Bf[nj][1]);
                mma_bf16(acc[mi][nj * 2 + 1], Ah[mi], Bf[nj][2], Bf[nj][3]);
            }
    };

    // prologue: chunk 0
    float4 pf[4];
    ldg_x(0, pf);
    stage_m(0, 0);
    conv_sts(0, pf);
    cp_wait0();
    __syncthreads();

#pragma unroll 1
    for (int kc = 0; kc < 8; kc++) {
        const int cur = kc & 1;
        if (kc < 7) stage_m(kc + 1, cur ^ 1);
        mma_half(0, cur);
        if (kc < 7) ldg_x(kc + 1, pf);
        mma_half(1, cur);
        if (kc < 7) {
            conv_sts(cur ^ 1, pf);
            cp_wait0();
        }
        __syncthreads();
    }

    // epilogue: split T to bf16 hi/lo and store
    __nv_bfloat16* th = g_Th + (size_t)z * N * N;
    __nv_bfloat16* tl = g_Tl + (size_t)z * N * N;
#pragma unroll
    for (int mi = 0; mi < 2; mi++)
#pragma unroll
        for (int nf = 0; nf < 8; nf++) {
            int col = nh * 128 + wn * 64 + nf * 8 + (lane & 3) * 2;
#pragma unroll
            for (int rg = 0; rg < 2; rg++) {
                int row = h * 128 + wm * 32 + mi * 16 + rg * 8 + (lane >> 2);
                float vx = acc[mi][nf][rg * 2], vy = acc[mi][nf][rg * 2 + 1];
                __nv_bfloat16 hx = __float2bfloat16_rn(vx);
                __nv_bfloat16 hy = __float2bfloat16_rn(vy);
                float lx = vx - __bfloat162float(hx);
                float ly = vy - __bfloat162float(hy);
                __nv_bfloat162 hp; hp.x = hx; hp.y = hy;
                size_t go = (size_t)row * N + col;
                *(uint32_t*)&th[go] = reinterpret_cast<uint32_t&>(hp);
                *(uint32_t*)&tl[go] = pkbf2(lx, ly);
            }
        }
}

// ---------------- MODE 2: out = T * M^T  (all operands bf16 hi/lo via cp.async)
// grid (NIMG, 2, 2) = (z, h, nh); warp tile 32x64. Pure ldsm+mma inner loop.
__global__ __launch_bounds__(256, 2) void k_mm2(float* __restrict__ Out,
                                                const int* __restrict__ steps) {
    extern __shared__ char sm[];
    const int z = blockIdx.x, h = blockIdx.y, nh = blockIdx.z;
    const int s = steps[z / 3];
    const int t = threadIdx.x, lane = t & 31, wid = t >> 5;
    const int wm = wid >> 1, wn = wid & 1;
    const uint32_t sb = smem_u32(sm);
    const int lr = lane & 15, lc8 = (lane >> 4) * 8;

    const char* Th_g = (const char*)(g_Th + (size_t)z * N * N);
    const char* Tl_g = (const char*)(g_Tl + (size_t)z * N * N);
    const char* Mh_g = (const char*)(g_Mh + (size_t)s * N * N);
    const char* Ml_g = (const char*)(g_Ml + (size_t)s * N * N);

    auto stage = [&](int kc, int d) {
        const uint32_t bo = sb + d * 40960;
#pragma unroll
        for (int i = 0; i < 2; i++) {
            int c = t + i * 256, r = c >> 2, q = c & 3;
            {   // A = T rows h*128..
                size_t go = (size_t)(h * 128 + r) * 512 + kc * 64 + q * 16;
                cp16(bo + r * 80 + q * 16, Th_g + go);
                cp16(bo + 10240 + r * 80 + q * 16, Tl_g + go);
            }
            {   // B = M rows nh*128..
                size_t go = (size_t)(nh * 128 + r) * 512 + kc * 64 + q * 16;
                cp16(bo + 20480 + r * 80 + q * 16, Mh_g + go);
                cp16(bo + 30720 + r * 80 + q * 16, Ml_g + go);
            }
        }
        cp_commit();
    };

    float acc[2][8][4];
#pragma unroll
    for (int a = 0; a < 2; a++)
#pragma unroll
        for (int b = 0; b < 8; b++)
#pragma unroll
            for (int c = 0; c < 4; c++) acc[a][b][c] = 0.0f;

    auto mma_half = [&](int ks, int d) {
        uint32_t Ah[2][4], Al2[2][4], Bf[4][4];
        const uint32_t bo = sb + d * 40960;
#pragma unroll
        for (int mi = 0; mi < 2; mi++) {
            uint32_t a = bo + ((wm * 32 + mi * 16 + lr) * 40 + ks * 16 + lc8) * 2;
            ldsm4(Ah[mi], a);
            ldsm4(Al2[mi], a + 10240);
        }
#pragma unroll
        for (int nj = 0; nj < 4; nj++) {
            uint32_t a = bo + 20480 + ((wn * 64 + nj * 16 + lr) * 40 + ks * 16 + lc8) * 2;
            ldsm4(Bf[nj], a);
        }
        // non-trans B pairing: {r0,r2} / {r1,r3}
        // pass 1: Ah x Bh
#pragma unroll
        for (int mi = 0; mi < 2; mi++)
#pragma unroll
            for (int nj = 0; nj < 4; nj++) {
                mma_bf16(acc[mi][nj * 2],     Ah[mi], Bf[nj][0], Bf[nj][2]);
                mma_bf16(acc[mi][nj * 2 + 1], Ah[mi], Bf[nj][1], Bf[nj][3]);
            }
        // pass 2: Al x Bh
#pragma unroll
        for (int mi = 0; mi < 2; mi++)
#pragma unroll
            for (int nj = 0; nj < 4; nj++) {
                mma_bf16(acc[mi][nj * 2],     Al2[mi], Bf[nj][0], Bf[nj][2]);
                mma_bf16(acc[mi][nj * 2 + 1], Al2[mi], Bf[nj][1], Bf[nj][3]);
            }
        // reload B lo
#pragma unroll
        for (int nj = 0; nj < 4; nj++) {
            uint32_t a = bo + 30720 + ((wn * 64 + nj * 16 + lr) * 40 + ks * 16 + lc8) * 2;
            ldsm4(Bf[nj], a);
        }
        // pass 3: Ah x Bl
#pragma unroll
        for (int mi = 0; mi < 2; mi++)
#pragma unroll
            for (int nj = 0; nj < 4; nj++) {
                mma_bf16(acc[mi][nj * 2],     Ah[mi], Bf[nj][0], Bf[nj][2]);
                mma_bf16(acc[mi][nj * 2 + 1], Ah[mi], Bf[nj][1], Bf[nj][3]);
            }
    };

    stage(0, 0);
    cp_wait0();
    __syncthreads();

#pragma unroll 1
    for (int kc = 0; kc < 8; kc++) {
        const int cur = kc & 1;
        if (kc < 7) stage(kc + 1, cur ^ 1);
        mma_half(0, cur);
        mma_half(1, cur);
        if (kc < 7) cp_wait0();
        __syncthreads();
    }

    float* dst = Out + (size_t)z * N * N;
#pragma unroll
    for (int mi = 0; mi < 2; mi++)
#pragma unroll
        for (int nf = 0; nf < 8; nf++) {
            int col = nh * 128 + wn * 64 + nf * 8 + (lane & 3) * 2;
#pragma unroll
            for (int rg = 0; rg < 2; rg++) {
                int row = h * 128 + wm * 32 + mi * 16 + rg * 8 + (lane >> 2);
                *(float2*)&dst[(size_t)row * N + col] =
                    make_float2(acc[mi][nf][rg * 2], acc[mi][nf][rg * 2 + 1]);
            }
        }
}

// ---------------- host ----------------
extern "C" void kernel_launch(void* const* d_in, const int* in_sizes, int n_in,
                              void* d_out, int out_size) {
    const float* x = nullptr;
    const float* sigmas = nullptr;
    const int* steps = nullptr;
    for (int i = 0; i < n_in; i++) {
        if (in_sizes[i] == NSTEPS)      sigmas = (const float*)d_in[i];
        else if (in_sizes[i] == 128)    steps  = (const int*)d_in[i];
        else                            x      = (const float*)d_in[i];
    }
    float* out = (float*)d_out;

    cudaFuncSetAttribute(k_mm1, cudaFuncAttributeMaxDynamicSharedMemorySize, M1_SMEM);
    cudaFuncSetAttribute(k_mm2, cudaFuncAttributeMaxDynamicSharedMemorySize, M2_SMEM);

    k_init<<<N, N>>>(sigmas);
    k_gemm0<<<dim3(N / BN, N / BM, NSTEPS), 256>>>();
    k_mm1<<<dim3(NIMG, 2, 2), 256, M1_SMEM>>>(x, steps);
    k_mm2<<<dim3(NIMG, 2, 2), 256, M2_SMEM>>>(out, steps);
}

// round 13
// speedup vs baseline: 1.4868x; 1.4868x over previous
#include <cuda_runtime.h>
#include <cuda_bf16.h>
#include <math.h>
#include <stdint.h>

namespace {
constexpr int N      = 256;
constexpr int NSTEPS = 32;
constexpr int NIMG   = 384;                  // 128 batch * 3 channels

// fp32 M-builder tile
constexpr int BM = 128, BN = 128, BK = 16;
constexpr int LDSW = BM + 4;

// ---- k_mm smem maps (bytes) ----
// MODE 1: per double-buffer: A hi 10240 | A lo 10240 | B fp32 stage 16896  = 37376
//         single convert dest: B hi 8704 | B lo 8704 at 2*BUFSZ
constexpr int M1_AH   = 0;
constexpr int M1_AL   = 10240;
constexpr int M1_BS   = 20480;
constexpr int M1_BUF  = 37376;
constexpr int M1_CBH  = 2 * M1_BUF;          // 74752
constexpr int M1_CBL  = M1_CBH + 8704;
constexpr int M1_SMEM = M1_CBL + 8704;       // 92160
// MODE 2: per double-buffer: A fp32 stage 18432 | B hi 10240 | B lo 10240 = 38912
//         single convert dest: A hi 10240 | A lo 10240 at 2*BUFSZ
constexpr int M2_AS   = 0;
constexpr int M2_BH   = 18432;
constexpr int M2_BL   = 28672;
constexpr int M2_BUF  = 38912;
constexpr int M2_CAH  = 2 * M2_BUF;          // 77824
constexpr int M2_CAL  = M2_CAH + 10240;
constexpr int M2_SMEM = M2_CAL + 10240;      // 98304
}

// ---------------- device globals ----------------
__device__ float g_D[N * N];
__device__ float g_E[NSTEPS * N];
__device__ __align__(16) __nv_bfloat16 g_Mh[NSTEPS * N * N];
__device__ __align__(16) __nv_bfloat16 g_Ml[NSTEPS * N * N];
__device__ __align__(16) float g_T[NIMG * N * N];     // fp32 intermediate

// ---------------- helpers ----------------
__device__ __forceinline__ uint32_t smem_u32(const void* p) {
    uint32_t a;
    asm("{ .reg .u64 t; cvta.to.shared.u64 t, %1; cvt.u32.u64 %0, t; }" : "=r"(a) : "l"(p));
    return a;
}
__device__ __forceinline__ void cp16(uint32_t s, const void* g) {
    asm volatile("cp.async.cg.shared.global [%0], [%1], 16;" :: "r"(s), "l"(g) : "memory");
}
__device__ __forceinline__ void cp_commit() {
    asm volatile("cp.async.commit_group;" ::: "memory");
}
__device__ __forceinline__ void cp_wait0() {
    asm volatile("cp.async.wait_group 0;" ::: "memory");
}
__device__ __forceinline__ void ldsm4(uint32_t* r, uint32_t a) {
    asm volatile("ldmatrix.sync.aligned.m8n8.x4.shared.b16 {%0,%1,%2,%3}, [%4];"
                 : "=r"(r[0]), "=r"(r[1]), "=r"(r[2]), "=r"(r[3]) : "r"(a));
}
__device__ __forceinline__ void ldsm4t(uint32_t* r, uint32_t a) {
    asm volatile("ldmatrix.sync.aligned.m8n8.x4.trans.shared.b16 {%0,%1,%2,%3}, [%4];"
                 : "=r"(r[0]), "=r"(r[1]), "=r"(r[2]), "=r"(r[3]) : "r"(a));
}
__device__ __forceinline__ void mma_bf16(float* d, const uint32_t* a, uint32_t b0, uint32_t b1) {
    asm volatile(
        "mma.sync.aligned.m16n8k16.row.col.f32.bf16.bf16.f32 "
        "{%0,%1,%2,%3}, {%4,%5,%6,%7}, {%8,%9}, {%0,%1,%2,%3};"
        : "+f"(d[0]), "+f"(d[1]), "+f"(d[2]), "+f"(d[3])
        : "r"(a[0]), "r"(a[1]), "r"(a[2]), "r"(a[3]), "r"(b0), "r"(b1));
}
__device__ __forceinline__ uint32_t pkbf2(float a, float b) {
    __nv_bfloat162 t = __floats2bfloat162_rn(a, b);
    return reinterpret_cast<uint32_t&>(t);
}
__device__ __forceinline__ void split8(const float* v, uint4& H, uint4& L) {
    float h[8], l[8];
#pragma unroll
    for (int i = 0; i < 8; i++) {
        __nv_bfloat16 b = __float2bfloat16_rn(v[i]);
        h[i] = __bfloat162float(b);
        l[i] = v[i] - h[i];
    }
    H = make_uint4(pkbf2(h[0], h[1]), pkbf2(h[2], h[3]), pkbf2(h[4], h[5]), pkbf2(h[6], h[7]));
    L = make_uint4(pkbf2(l[0], l[1]), pkbf2(l[2], l[3]), pkbf2(l[4], l[5]), pkbf2(l[6], l[7]));
}
__device__ __forceinline__ void split4(float4 v, uint2& H, uint2& L) {
    float vv[4] = {v.x, v.y, v.z, v.w};
    float h[4], l[4];
#pragma unroll
    for (int i = 0; i < 4; i++) {
        __nv_bfloat16 b = __float2bfloat16_rn(vv[i]);
        h[i] = __bfloat162float(b);
        l[i] = vv[i] - h[i];
    }
    H = make_uint2(pkbf2(h[0], h[1]), pkbf2(h[2], h[3]));
    L = make_uint2(pkbf2(l[0], l[1]), pkbf2(l[2], l[3]));
}

// ---------------- init: D and E ----------------
__global__ void k_init(const float* __restrict__ sigmas) {
    int k = blockIdx.x, n = threadIdx.x;
    int p = ((2 * n + 1) * k) & (4 * N - 1);
    double v = sqrt(2.0 / (double)N) * cos(M_PI * (double)p / (double)(2 * N));
    if (k == 0) v *= 0.7071067811865476;
    g_D[k * N + n] = (float)v;
    if (k < NSTEPS) {
        float sig = sigmas[k];
        float t = 0.5f * sig * sig;
        float f = (float)M_PI * (float)n / (float)N;
        g_E[k * N + n] = expf(-f * f * t);
    }
}

// ---------------- fp32 builder: M_s = (D diag(e)) D, split epilogue ----------------
typedef unsigned long long u64;
__device__ __forceinline__ u64 pack2(float x, float y) {
    u64 r; asm("mov.b64 %0, {%1, %2};" : "=l"(r) : "f"(x), "f"(y)); return r;
}
__device__ __forceinline__ void unpack2(u64 v, float& x, float& y) {
    asm("mov.b64 {%0, %1}, %2;" : "=f"(x), "=f"(y) : "l"(v));
}
__device__ __forceinline__ void ffma2(u64& d, u64 a, u64 b) {
    asm("fma.rn.f32x2 %0, %1, %2, %0;" : "+l"(d) : "l"(a), "l"(b));
}

__global__ __launch_bounds__(256, 2) void k_gemm0() {
    __shared__ float As[BK][LDSW];
    __shared__ float Bs[BK][LDSW];
    const int z = blockIdx.z;
    const float* A = g_D;
    const float* B = g_D;
    const float* e = g_E + z * N;
    __nv_bfloat16* Ch = g_Mh + (size_t)z * N * N;
    __nv_bfloat16* Cl = g_Ml + (size_t)z * N * N;

    const int m0 = blockIdx.y * BM, n0 = blockIdx.x * BN;
    const int tid = threadIdx.x;
    const int ty = tid >> 4, tx = tid & 15;
    const int lr = (tid * 2) >> 2, lc = (tid * 2) & 3;
    const int bkr = (tid * 2) >> 5, bnc = (tid * 2) & 31;

    u64 acc[8][4];
#pragma unroll
    for (int i = 0; i < 8; i++)
#pragma unroll
        for (int j = 0; j < 4; j++) acc[i][j] = 0ull;

    for (int k0 = 0; k0 < N; k0 += BK) {
        float4 a0 = *(const float4*)&A[(size_t)(m0 + lr) * N + k0 + lc * 4];
        float4 a1 = *(const float4*)&A[(size_t)(m0 + lr) * N + k0 + lc * 4 + 4];
        a0.x *= e[k0 + lc * 4 + 0]; a0.y *= e[k0 + lc * 4 + 1];
        a0.z *= e[k0 + lc * 4 + 2]; a0.w *= e[k0 + lc * 4 + 3];
        a1.x *= e[k0 + lc * 4 + 4]; a1.y *= e[k0 + lc * 4 + 5];
        a1.z *= e[k0 + lc * 4 + 6]; a1.w *= e[k0 + lc * 4 + 7];
        float4 b0 = *(const float4*)&B[(size_t)(k0 + bkr) * N + n0 + bnc * 4];
        float4 b1 = *(const float4*)&B[(size_t)(k0 + bkr) * N + n0 + bnc * 4 + 4];
        __syncthreads();
        As[lc * 4 + 0][lr] = a0.x; As[lc * 4 + 1][lr] = a0.y;
        As[lc * 4 + 2][lr] = a0.z; As[lc * 4 + 3][lr] = a0.w;
        As[lc * 4 + 4][lr] = a1.x; As[lc * 4 + 5][lr] = a1.y;
        As[lc * 4 + 6][lr] = a1.z; As[lc * 4 + 7][lr] = a1.w;
        *(float4*)&Bs[bkr][bnc * 4]     = b0;
        *(float4*)&Bs[bkr][bnc * 4 + 4] = b1;
        __syncthreads();
#pragma unroll
        for (int kk = 0; kk < BK; kk++) {
            float4 av0 = *(const float4*)&As[kk][ty * 4];
            float4 av1 = *(const float4*)&As[kk][64 + ty * 4];
            float4 bv0 = *(const float4*)&Bs[kk][tx * 4];
            float4 bv1 = *(const float4*)&Bs[kk][64 + tx * 4];
            u64 a2[8] = {pack2(av0.x, av0.x), pack2(av0.y, av0.y), pack2(av0.z, av0.z),
                         pack2(av0.w, av0.w), pack2(av1.x, av1.x), pack2(av1.y, av1.y),
                         pack2(av1.z, av1.z), pack2(av1.w, av1.w)};
            u64 b2[4] = {pack2(bv0.x, bv0.y), pack2(bv0.z, bv0.w),
                         pack2(bv1.x, bv1.y), pack2(bv1.z, bv1.w)};
#pragma unroll
            for (int i = 0; i < 8; i++)
#pragma unroll
                for (int j = 0; j < 4; j++) ffma2(acc[i][j], a2[i], b2[j]);
        }
    }
    // epilogue: split fp32 -> bf16 hi/lo directly (no fp32 g_M round trip)
#pragma unroll
    for (int i = 0; i < 8; i++) {
        const int row = m0 + ((i < 4) ? (ty * 4 + i) : (64 + ty * 4 + (i - 4)));
        float4 c0, c1;
        unpack2(acc[i][0], c0.x, c0.y); unpack2(acc[i][1], c0.z, c0.w);
        unpack2(acc[i][2], c1.x, c1.y); unpack2(acc[i][3], c1.z, c1.w);
        uint2 H0, L0, H1, L1;
        split4(c0, H0, L0);
        split4(c1, H1, L1);
        *(uint2*)&Ch[(size_t)row * N + n0 + tx * 4]      = H0;
        *(uint2*)&Cl[(size_t)row * N + n0 + tx * 4]      = L0;
        *(uint2*)&Ch[(size_t)row * N + n0 + 64 + tx * 4] = H1;
        *(uint2*)&Cl[(size_t)row * N + n0 + 64 + tx * 4] = L1;
    }
}

// ---------------- MMA kernel (R6 champion structure) ----------------
// grid (NIMG, 2, 2) = (z, h, nh); 256 threads; warp grid 4m x 2n; warp tile 32x64.
// MODE 1: T[z](h,nh) = M[s](h rows) * X[z]        (B = fp32 X, split in-kernel)
// MODE 2: out[z](h,nh) = T[z](h rows) * M[s]^T    (A = fp32 T, split in-kernel)
template <int MODE>
__global__ __launch_bounds__(256, 2) void k_mm(const float* __restrict__ Xf,
                                               float* __restrict__ Out,
                                               const int* __restrict__ steps) {
    extern __shared__ char sm[];
    const int z = blockIdx.x, h = blockIdx.y, nh = blockIdx.z;
    const int s = steps[z / 3];
    const int t = threadIdx.x, lane = t & 31, wid = t >> 5;
    const int wm = wid >> 1, wn = wid & 1;
    const uint32_t sb = smem_u32(sm);
    const int lr = lane & 15, lc8 = (lane >> 4) * 8;

    constexpr int BUFSZ = (MODE == 1) ? M1_BUF : M2_BUF;

    const char* Mh_g = (const char*)(g_Mh + (size_t)s * N * N);
    const char* Ml_g = (const char*)(g_Ml + (size_t)s * N * N);
    const float* F_g = (MODE == 1) ? (Xf + (size_t)z * N * N)
                                   : (g_T + (size_t)z * N * N);

    auto stage = [&](int kc, int b) {
        const uint32_t bo = sb + b * BUFSZ;
        if (MODE == 1) {
            // A = M hi/lo direct: 128 rows x 64B, tile col offset kc*64
#pragma unroll
            for (int i = 0; i < 2; i++) {
                int c = t + i * 256, r = c >> 2, q = c & 3;
                size_t go = (size_t)(h * 128 + r) * 512 + kc * 64 + q * 16;
                cp16(bo + M1_AH + r * 80 + q * 16, Mh_g + go);
                cp16(bo + M1_AL + r * 80 + q * 16, Ml_g + go);
            }
            // B = X fp32: rows kc*32..+32, cols nh*128..+128 (512B per row slice)
#pragma unroll
            for (int i = 0; i < 4; i++) {
                int c = t + i * 256, r = c >> 5, q = c & 31;
                size_t go = (size_t)(kc * 32 + r) * 1024 + nh * 512 + q * 16;
                cp16(bo + M1_BS + r * 528 + q * 16, (const char*)F_g + go);
            }
        } else {
            // A = T fp32: rows h*128..+128, cols kc*32..+32 (128B per row slice)
#pragma unroll
            for (int i = 0; i < 4; i++) {
                int c = t + i * 256, r = c >> 3, q = c & 7;
                size_t go = (size_t)(h * 128 + r) * 1024 + kc * 128 + q * 16;
                cp16(bo + M2_AS + r * 144 + q * 16, (const char*)F_g + go);
            }
            // B = M hi/lo direct: rows nh*128..+128 x 64B, col offset kc*64
#pragma unroll
            for (int i = 0; i < 2; i++) {
                int c = t + i * 256, r = c >> 2, q = c & 3;
                size_t go = (size_t)(nh * 128 + r) * 512 + kc * 64 + q * 16;
                cp16(bo + M2_BH + r * 80 + q * 16, Mh_g + go);
                cp16(bo + M2_BL + r * 80 + q * 16, Ml_g + go);
            }
        }
        cp_commit();
    };

    float acc[2][8][4];
#pragma unroll
    for (int a = 0; a < 2; a++)
#pragma unroll
        for (int b = 0; b < 8; b++)
#pragma unroll
            for (int c = 0; c < 4; c++) acc[a][b][c] = 0.0f;

    stage(0, 0);

#pragma unroll 1
    for (int kc = 0; kc < 8; kc++) {
        cp_wait0();
        __syncthreads();
        if (kc < 7) stage(kc + 1, (kc + 1) & 1);
        const uint32_t bo = sb + (kc & 1) * BUFSZ;
        const char* bufc = sm + (kc & 1) * BUFSZ;

        // convert staged fp32 -> bf16 hi/lo (single-buffered dest)
        if (MODE == 1) {
            // 32 x 128 fp32, stride 132 -> dest stride 136
            int r = t >> 3, cs = (t & 7) * 16;
            const float* src = (const float*)(bufc + M1_BS) + r * 132 + cs;
            char* dh = sm + M1_CBH + (r * 136 + cs) * 2;
            char* dl = sm + M1_CBL + (r * 136 + cs) * 2;
#pragma unroll
            for (int g = 0; g < 2; g++) {
                float4 v0 = *(const float4*)&src[g * 8];
                float4 v1 = *(const float4*)&src[g * 8 + 4];
                float v[8] = {v0.x, v0.y, v0.z, v0.w, v1.x, v1.y, v1.z, v1.w};
                uint4 H, L; split8(v, H, L);
                *(uint4*)(dh + g * 16) = H;
                *(uint4*)(dl + g * 16) = L;
            }
        } else {
            // 128 x 32 fp32, stride 36 -> dest stride 40
            int r = t >> 1, cs = (t & 1) * 16;
            const float* src = (const float*)(bufc + M2_AS) + r * 36 + cs;
            char* dh = sm + M2_CAH + (r * 40 + cs) * 2;
            char* dl = sm + M2_CAL + (r * 40 + cs) * 2;
#pragma unroll
            for (int g = 0; g < 2; g++) {
                float4 v0 = *(const float4*)&src[g * 8];
                float4 v1 = *(const float4*)&src[g * 8 + 4];
                float v[8] = {v0.x, v0.y, v0.z, v0.w, v1.x, v1.y, v1.z, v1.w};
                uint4 H, L; split8(v, H, L);
                *(uint4*)(dh + g * 16) = H;
                *(uint4*)(dl + g * 16) = L;
            }
        }
        __syncthreads();

#pragma unroll
        for (int ks = 0; ks < 2; ks++) {
            uint32_t Ah[2][4], Al2[2][4], Bf[4][4];
            // A fragments (hi + lo)
#pragma unroll
            for (int mi = 0; mi < 2; mi++) {
                uint32_t a;
                if (MODE == 1)
                    a = bo + M1_AH + ((wm * 32 + mi * 16 + lr) * 40 + ks * 16 + lc8) * 2;
                else
                    a = sb + M2_CAH + ((wm * 32 + mi * 16 + lr) * 40 + ks * 16 + lc8) * 2;
                ldsm4(Ah[mi], a);
                ldsm4(Al2[mi], a + ((MODE == 1) ? (M1_AL - M1_AH) : (M2_CAL - M2_CAH)));
            }
            // B hi fragments
#pragma unroll
            for (int nj = 0; nj < 4; nj++) {
                if (MODE == 1) {
                    uint32_t a = sb + M1_CBH + ((ks * 16 + lr) * 136 + wn * 64 + nj * 16 + lc8) * 2;
                    ldsm4t(Bf[nj], a);
                } else {
                    uint32_t a = bo + M2_BH + ((wn * 64 + nj * 16 + lr) * 40 + ks * 16 + lc8) * 2;
                    ldsm4(Bf[nj], a);
                }
            }
            const int p0 = 0, p1 = (MODE == 1) ? 1 : 2;
            const int p2 = (MODE == 1) ? 2 : 1, p3 = 3;
            // pass 1: Ah x Bh — all-distinct accumulators
#pragma unroll
            for (int mi = 0; mi < 2; mi++)
#pragma unroll
                for (int nj = 0; nj < 4; nj++) {
                    mma_bf16(acc[mi][nj * 2],     Ah[mi], Bf[nj][p0], Bf[nj][p1]);
                    mma_bf16(acc[mi][nj * 2 + 1], Ah[mi], Bf[nj][p2], Bf[nj][p3]);
                }
            // pass 2: Al x Bh
#pragma unroll
            for (int mi = 0; mi < 2; mi++)
#pragma unroll
                for (int nj = 0; nj < 4; nj++) {
                    mma_bf16(acc[mi][nj * 2],     Al2[mi], Bf[nj][p0], Bf[nj][p1]);
                    mma_bf16(acc[mi][nj * 2 + 1], Al2[mi], Bf[nj][p2], Bf[nj][p3]);
                }
            // B lo fragments (reuse Bf registers)
#pragma unroll
            for (int nj = 0; nj < 4; nj++) {
                if (MODE == 1) {
                    uint32_t a = sb + M1_CBL + ((ks * 16 + lr) * 136 + wn * 64 + nj * 16 + lc8) * 2;
                    ldsm4t(Bf[nj], a);
                } else {
                    uint32_t a = bo + M2_BL + ((wn * 64 + nj * 16 + lr) * 40 + ks * 16 + lc8) * 2;
                    ldsm4(Bf[nj], a);
                }
            }
            // pass 3: Ah x Bl
#pragma unroll
            for (int mi = 0; mi < 2; mi++)
#pragma unroll
                for (int nj = 0; nj < 4; nj++) {
                    mma_bf16(acc[mi][nj * 2],     Ah[mi], Bf[nj][p0], Bf[nj][p1]);
                    mma_bf16(acc[mi][nj * 2 + 1], Ah[mi], Bf[nj][p2], Bf[nj][p3]);
                }
        }
        __syncthreads();
    }

    // epilogue: fp32 store (T or Out)
    float* dst = ((MODE == 1) ? g_T : Out) + (size_t)z * N * N;
#pragma unroll
    for (int mi = 0; mi < 2; mi++)
#pragma unroll
        for (int nf = 0; nf < 8; nf++) {
            int col = nh * 128 + wn * 64 + nf * 8 + (lane & 3) * 2;
#pragma unroll
            for (int rg = 0; rg < 2; rg++) {
                int row = h * 128 + wm * 32 + mi * 16 + rg * 8 + (lane >> 2);
                *(float2*)&dst[(size_t)row * N + col] =
                    make_float2(acc[mi][nf][rg * 2], acc[mi][nf][rg * 2 + 1]);
            }
        }
}

// ---------------- host ----------------
extern "C" void kernel_launch(void* const* d_in, const int* in_sizes, int n_in,
                              void* d_out, int out_size) {
    const float* x = nullptr;
    const float* sigmas = nullptr;
    const int* steps = nullptr;
    for (int i = 0; i < n_in; i++) {
        if (in_sizes[i] == NSTEPS)      sigmas = (const float*)d_in[i];
        else if (in_sizes[i] == 128)    steps  = (const int*)d_in[i];
        else                            x      = (const float*)d_in[i];
    }
    float* out = (float*)d_out;

    cudaFuncSetAttribute(k_mm<1>, cudaFuncAttributeMaxDynamicSharedMemorySize, M1_SMEM);
    cudaFuncSetAttribute(k_mm<2>, cudaFuncAttributeMaxDynamicSharedMemorySize, M2_SMEM);

    k_init<<<N, N>>>(sigmas);
    k_gemm0<<<dim3(N / BN, N / BM, NSTEPS), 256>>>();
    k_mm<1><<<dim3(NIMG, 2, 2), 256, M1_SMEM>>>(x, nullptr, steps);
    k_mm<2><<<dim3(NIMG, 2, 2), 256, M2_SMEM>>>(nullptr, out, steps);
}